// round 9
// baseline (speedup 1.0000x reference)
#include <cuda_runtime.h>
#include <cuda_bf16.h>
#include <cstdint>

#define NITER   50
#define EPSF    0.1f
#define PCOEF   (1.0f/1.1f)
#define LOGHUGE 69.07755279f   /* log(1e30) */
#define NB      256
#define NN      256
#define KPAD    264            /* padded row length (bf16): 528B stride -> ldmatrix conflict-free */
#define DXC     (1.0f/256.0f)
#define DYC     (1.0f/256.0f)
#define PI2F    1.57079632679489662f

typedef unsigned long long u64;

struct __align__(16) Smem {
    uint16_t K0[NN * KPAD];   // 135168 B bf16 kernel matrix
    uint16_t zbp[NN];         // bf16 z, B-frag (pidx) order
    uint16_t wbp[NN];         // bf16 w, B-frag (pidx) order
    float rp[2][NN];          // row partials per k-half
    float cp[2][NN];          // col partials per i-half
    float z[NN];              // f32 (epilogue)
    float w[NN];
    float csave[NN];
    float part[8][NN];        // epilogue scratch
    float red[8];
};

__device__ __forceinline__ unsigned pack_bf16(float a, float b) {
    __nv_bfloat162 h = __floats2bfloat162_rn(a, b);
    return *reinterpret_cast<unsigned*>(&h);
}
__device__ __forceinline__ uint16_t to_bf16u(float a) {
    __nv_bfloat16 h = __float2bfloat16(a);
    return *reinterpret_cast<uint16_t*>(&h);
}
__device__ __forceinline__ int pidx(int j) {
    return (j & ~15) | (((j & 7) >> 1) << 2) | (((j >> 3) & 1) << 1) | (j & 1);
}
__device__ __forceinline__ void ldmx4(uint32_t addr, uint32_t& r0, uint32_t& r1, uint32_t& r2, uint32_t& r3) {
    asm volatile("ldmatrix.sync.aligned.m8n8.x4.shared.b16 {%0,%1,%2,%3}, [%4];"
                 : "=r"(r0), "=r"(r1), "=r"(r2), "=r"(r3) : "r"(addr));
}
__device__ __forceinline__ void ldmx4t(uint32_t addr, uint32_t& r0, uint32_t& r1, uint32_t& r2, uint32_t& r3) {
    asm volatile("ldmatrix.sync.aligned.m8n8.x4.trans.shared.b16 {%0,%1,%2,%3}, [%4];"
                 : "=r"(r0), "=r"(r1), "=r"(r2), "=r"(r3) : "r"(addr));
}
__device__ __forceinline__ void mma_bf16(float& d0, float& d1, float& d2, float& d3,
                                         uint32_t a0, uint32_t a1, uint32_t a2, uint32_t a3,
                                         uint32_t b0, uint32_t b1) {
    asm volatile("mma.sync.aligned.m16n8k16.row.col.f32.bf16.bf16.f32 "
                 "{%0,%1,%2,%3},{%4,%5,%6,%7},{%8,%9},{%0,%1,%2,%3};"
                 : "+f"(d0), "+f"(d1), "+f"(d2), "+f"(d3)
                 : "r"(a0), "r"(a1), "r"(a2), "r"(a3), "r"(b0), "r"(b1));
}
__device__ __forceinline__ void pair_bar(int id) {
    asm volatile("bar.sync %0, %1;" :: "r"(id), "r"(128) : "memory");
}

__global__ void __launch_bounds__(1024, 1)
wfr_kernel(const float* __restrict__ D, float* __restrict__ out)
{
    extern __shared__ char smraw[];
    Smem* sm = reinterpret_cast<Smem*>(smraw);
    const int b = blockIdx.x;
    const int t = threadIdx.x;
    const float* __restrict__ Db = D + (size_t)b * (NN * NN);

    // ---------------- Prologue: K0 = (cos(min(2D,pi/2)) + 1e-5)^20  (bf16, SMEM) ---------
    {
        const float4* __restrict__ D4 = reinterpret_cast<const float4*>(Db);
        #pragma unroll 4
        for (int k = 0; k < 16; k++) {
            int i4 = t + k * 1024;
            float4 d = D4[i4];
            int e = i4 << 2;
            int i = e >> 8, j = e & (NN - 1);
            float c0 = __cosf(fminf(d.x * 2.0f, PI2F)) + 1e-5f;
            float c1 = __cosf(fminf(d.y * 2.0f, PI2F)) + 1e-5f;
            float c2 = __cosf(fminf(d.z * 2.0f, PI2F)) + 1e-5f;
            float c3 = __cosf(fminf(d.w * 2.0f, PI2F)) + 1e-5f;
            float k0 = exp2f(20.0f * __log2f(c0));
            float k1 = exp2f(20.0f * __log2f(c1));
            float k2 = exp2f(20.0f * __log2f(c2));
            float k3 = exp2f(20.0f * __log2f(c3));
            uint2 pk = make_uint2(pack_bf16(k0, k1), pack_bf16(k2, k3));
            *reinterpret_cast<uint2*>(&sm->K0[i * KPAD + j]) = pk;
        }
        if (t < NN / 2) reinterpret_cast<uint32_t*>(sm->zbp)[t] = 0x3F803F80u; // z = 1
    }
    __syncthreads();

    const int lane    = t & 31;
    const int wp      = t >> 5;          // 32 warps
    const int half    = wp >> 4;         // k-half (row pass) / i-half (col pass)
    const int wmod    = wp & 15;
    const int rowbase = wmod << 4;       // 16 rows / 16 cols per warp group
    const bool owner  = (lane & 3) == 0;
    const int  oidx   = rowbase + (lane >> 2);
    const int  q      = lane & 3;
    const int  barid  = 1 + (wmod & 7);

    const uint32_t k0base = (uint32_t)__cvta_generic_to_shared(sm->K0);
    const uint32_t addrRow = k0base + 2u * ((rowbase + (lane & 15)) * KPAD + half * 128 + ((lane >> 4) << 3));
    const uint32_t addrCol = k0base + 2u * (((lane & 7) + ((lane & 16) >> 1) + (half << 7)) * KPAD
                                            + rowbase + (lane & 8));
    const uint32_t zbase = (uint32_t)__cvta_generic_to_shared(sm->zbp) + q * 8 + half * 256;
    const uint32_t wbase = (uint32_t)__cvta_generic_to_shared(sm->wbp) + q * 8 + half * 256;

    // ---- row-pass A fragments: 16 rows x this k-half, loaded ONCE (32 regs) ----
    uint32_t A0[8], A1[8], A2[8], A3[8];
    #pragma unroll
    for (int cc = 0; cc < 8; cc++)
        ldmx4(addrRow + cc * 32, A0[cc], A1[cc], A2[cc], A3[cc]);

    float u0 = 0.0f, u1 = 0.0f;     // potentials for rows oidx, oidx+8 (redundant in both halves)
    float v0 = 0.0f, v1 = 0.0f;     // potentials for cols oidx, oidx+8

    // ---------------- 50 Sinkhorn iterations ----------------
    #pragma unroll 1
    for (int it = 0; it < NITER; it++) {
        // ---- row pass: partial r_i over this k-half ----
        {
            float d0 = 0.f, d1 = 0.f, d2 = 0.f, d3 = 0.f;
            float e0 = 0.f, e1 = 0.f, e2 = 0.f, e3 = 0.f;
            #pragma unroll
            for (int cc = 0; cc < 8; cc += 2) {
                u64 p0, p1;
                asm volatile("ld.shared.b64 %0, [%1];" : "=l"(p0) : "r"(zbase + cc * 32));
                asm volatile("ld.shared.b64 %0, [%1];" : "=l"(p1) : "r"(zbase + cc * 32 + 32));
                mma_bf16(d0, d1, d2, d3, A0[cc], A1[cc], A2[cc], A3[cc],
                         (uint32_t)p0, (uint32_t)(p0 >> 32));
                mma_bf16(e0, e1, e2, e3, A0[cc + 1], A1[cc + 1], A2[cc + 1], A3[cc + 1],
                         (uint32_t)p1, (uint32_t)(p1 >> 32));
            }
            if (owner) {
                sm->rp[half][oidx]     = d0 + e0;
                sm->rp[half][oidx + 8] = d2 + e2;
            }
        }
        pair_bar(barid);
        if (owner) {
            float rA = sm->rp[0][oidx]     + sm->rp[1][oidx];
            float rB = sm->rp[0][oidx + 8] + sm->rp[1][oidx + 8];
            float la0 = fminf(-PCOEF * (11.0f * u0 + __logf(DYC * rA)), LOGHUGE);
            float la1 = fminf(-PCOEF * (11.0f * u1 + __logf(DYC * rB)), LOGHUGE);
            u0 += EPSF * la0;
            u1 += EPSF * la1;
            if (half == 0) {
                sm->wbp[pidx(oidx)]     = to_bf16u(__expf(10.0f * u0));
                sm->wbp[pidx(oidx + 8)] = to_bf16u(__expf(10.0f * u1));
            }
        }
        __syncthreads();

        // ---- col pass: partial c_j over this i-half (streamed transposed ldmatrix) ----
        {
            float d0 = 0.f, d1 = 0.f, d2 = 0.f, d3 = 0.f;
            float e0 = 0.f, e1 = 0.f, e2 = 0.f, e3 = 0.f;
            #pragma unroll
            for (int cc = 0; cc < 8; cc += 2) {
                u64 p0, p1;
                asm volatile("ld.shared.b64 %0, [%1];" : "=l"(p0) : "r"(wbase + cc * 32));
                asm volatile("ld.shared.b64 %0, [%1];" : "=l"(p1) : "r"(wbase + cc * 32 + 32));
                uint32_t a0, a1, a2, a3;
                ldmx4t(addrCol + cc * (32 * KPAD), a0, a1, a2, a3);
                mma_bf16(d0, d1, d2, d3, a0, a1, a2, a3,
                         (uint32_t)p0, (uint32_t)(p0 >> 32));
                ldmx4t(addrCol + (cc + 1) * (32 * KPAD), a0, a1, a2, a3);
                mma_bf16(e0, e1, e2, e3, a0, a1, a2, a3,
                         (uint32_t)p1, (uint32_t)(p1 >> 32));
            }
            if (owner) {
                sm->cp[half][oidx]     = d0 + e0;
                sm->cp[half][oidx + 8] = d2 + e2;
            }
        }
        pair_bar(barid);
        if (owner) {
            float cA = sm->cp[0][oidx]     + sm->cp[1][oidx];
            float cB = sm->cp[0][oidx + 8] + sm->cp[1][oidx + 8];
            float lb0 = fminf(-PCOEF * (11.0f * v0 + __logf(DXC * cA)), LOGHUGE);
            float lb1 = fminf(-PCOEF * (11.0f * v1 + __logf(DXC * cB)), LOGHUGE);
            v0 += EPSF * lb0;
            v1 += EPSF * lb1;
            if (half == 0) {
                sm->zbp[pidx(oidx)]     = to_bf16u(__expf(10.0f * v0));
                sm->zbp[pidx(oidx + 8)] = to_bf16u(__expf(10.0f * v1));
            }
        }
        __syncthreads();
    }

    // publish final f32 state for the epilogue
    if (owner && half == 0) {
        sm->w[oidx]     = __expf(10.0f * u0);
        sm->w[oidx + 8] = __expf(10.0f * u1);
        sm->z[oidx]     = __expf(10.0f * v0);
        sm->z[oidx + 8] = __expf(10.0f * v1);
    }
    if (t < NN) sm->csave[t] = sm->cp[0][t] + sm->cp[1][t];
    __syncthreads();

    // ---------------- Epilogue: marginals + transport --------------------------------
    const int row = t & (NN - 1);
    const int qt  = t >> 8;           // column quarter 0..3 (64 cols each)
    {
        const uint16_t* __restrict__ kr = sm->K0 + row * KPAD + qt * 64;
        const float*    __restrict__ zh = sm->z + qt * 64;
        const float*    __restrict__ dr = Db + row * NN + qt * 64;
        float racc = 0.f, tacc = 0.f;
        #pragma unroll 2
        for (int c = 0; c < 8; c++) {
            uint4  k4 = *reinterpret_cast<const uint4*>(kr + c * 8);
            float4 z0 = *reinterpret_cast<const float4*>(zh + c * 8);
            float4 z1 = *reinterpret_cast<const float4*>(zh + c * 8 + 4);
            float4 d0 = *reinterpret_cast<const float4*>(dr + c * 8);
            float4 d1 = *reinterpret_cast<const float4*>(dr + c * 8 + 4);

            float kz, cc, Cv;
            kz = __uint_as_float(k4.x << 16)          * z0.x; racc += kz;
            cc = __cosf(fminf(d0.x * 2.0f, PI2F)) + 1e-5f; Cv = -2.0f * __logf(cc); tacc = fmaf(kz, Cv, tacc);
            kz = __uint_as_float(k4.x & 0xFFFF0000u)  * z0.y; racc += kz;
            cc = __cosf(fminf(d0.y * 2.0f, PI2F)) + 1e-5f; Cv = -2.0f * __logf(cc); tacc = fmaf(kz, Cv, tacc);
            kz = __uint_as_float(k4.y << 16)          * z0.z; racc += kz;
            cc = __cosf(fminf(d0.z * 2.0f, PI2F)) + 1e-5f; Cv = -2.0f * __logf(cc); tacc = fmaf(kz, Cv, tacc);
            kz = __uint_as_float(k4.y & 0xFFFF0000u)  * z0.w; racc += kz;
            cc = __cosf(fminf(d0.w * 2.0f, PI2F)) + 1e-5f; Cv = -2.0f * __logf(cc); tacc = fmaf(kz, Cv, tacc);
            kz = __uint_as_float(k4.z << 16)          * z1.x; racc += kz;
            cc = __cosf(fminf(d1.x * 2.0f, PI2F)) + 1e-5f; Cv = -2.0f * __logf(cc); tacc = fmaf(kz, Cv, tacc);
            kz = __uint_as_float(k4.z & 0xFFFF0000u)  * z1.y; racc += kz;
            cc = __cosf(fminf(d1.y * 2.0f, PI2F)) + 1e-5f; Cv = -2.0f * __logf(cc); tacc = fmaf(kz, Cv, tacc);
            kz = __uint_as_float(k4.w << 16)          * z1.z; racc += kz;
            cc = __cosf(fminf(d1.z * 2.0f, PI2F)) + 1e-5f; Cv = -2.0f * __logf(cc); tacc = fmaf(kz, Cv, tacc);
            kz = __uint_as_float(k4.w & 0xFFFF0000u)  * z1.w; racc += kz;
            cc = __cosf(fminf(d1.w * 2.0f, PI2F)) + 1e-5f; Cv = -2.0f * __logf(cc); tacc = fmaf(kz, Cv, tacc);
        }
        sm->part[qt][row]     = racc;
        sm->part[4 + qt][row] = tacc;
    }
    __syncthreads();

    float val = 0.0f;
    if (t < NN) {
        float w_  = sm->w[t];
        float rm  = DYC * w_ * (sm->part[0][t] + sm->part[1][t] + sm->part[2][t] + sm->part[3][t]);
        float klr = rm * __logf(rm + 1e-10f) - rm + 1.0f;
        float tp  = w_ * (sm->part[4][t] + sm->part[5][t] + sm->part[6][t] + sm->part[7][t]) * (DXC * DYC);
        float cm  = DXC * sm->z[t] * sm->csave[t];
        float klc = cm * __logf(cm + 1e-10f) - cm + 1.0f;
        val = klr * DXC + klc * DYC + tp;
    }
    #pragma unroll
    for (int o = 16; o; o >>= 1) val += __shfl_down_sync(0xFFFFFFFFu, val, o);
    if (t < NN && lane == 0) sm->red[wp] = val;
    __syncthreads();
    if (t == 0) {
        float s = 0.0f;
        #pragma unroll
        for (int i = 0; i < 8; i++) s += sm->red[i];
        out[b] = s;
    }
}

extern "C" void kernel_launch(void* const* d_in, const int* in_sizes, int n_in,
                              void* d_out, int out_size)
{
    const float* D = (const float*)d_in[0];
    float* out = (float*)d_out;
    (void)in_sizes; (void)n_in; (void)out_size;
    size_t smem = sizeof(Smem);
    cudaFuncSetAttribute(wfr_kernel, cudaFuncAttributeMaxDynamicSharedMemorySize, (int)smem);
    wfr_kernel<<<NB, 1024, smem>>>(D, out);
}

// round 11
// speedup vs baseline: 1.2045x; 1.2045x over previous
#include <cuda_runtime.h>
#include <cuda_bf16.h>
#include <cstdint>

#define NITER   50
#define EPSF    0.1f
#define PCOEF   (1.0f/1.1f)
#define LOGHUGE 69.07755279f   /* log(1e30) */
#define NB      256
#define NN      256
#define KPAD    264            /* padded row length (bf16): 528B stride -> ldmatrix conflict-free */
#define DXC     (1.0f/256.0f)
#define DYC     (1.0f/256.0f)
#define PI2F    1.57079632679489662f

typedef unsigned long long u64;

struct __align__(16) Smem {
    uint16_t K0[NN * KPAD];   // 135168 B, bf16 kernel matrix K0 = exp(-C/eps)
    float z[NN];              // f32 z (epilogue only)
    float w[NN];              // f32 w (epilogue only)
    float csave[NN];          // final col sums (epilogue only)
    uint16_t zbp[NN];         // packed bf16 z in chunk-pair B-frag (pidx2) order
    uint16_t wbp[NN];         // packed bf16 w in pidx2 order
    float part[4][NN];        // epilogue scratch
    float red[16];
};

__device__ __forceinline__ unsigned pack_bf16(float a, float b) {
    __nv_bfloat162 h = __floats2bfloat162_rn(a, b);
    return *reinterpret_cast<unsigned*>(&h);
}
__device__ __forceinline__ uint16_t to_bf16u(float a) {
    __nv_bfloat16 h = __float2bfloat16(a);
    return *reinterpret_cast<uint16_t*>(&h);
}
// chunk-pair packed index: pair block of 32 values; thread q gets 16B:
// [chunk even: h0e0,h0e1,h1e0,h1e1][chunk odd: same]
__device__ __forceinline__ int pidx2(int j) {
    int chunk = j >> 4;
    int pair  = chunk >> 1;
    int odd   = chunk & 1;
    int q     = (j & 7) >> 1;
    int h     = (j >> 3) & 1;
    int e     = j & 1;
    return pair * 32 + q * 8 + odd * 4 + h * 2 + e;
}
__device__ __forceinline__ void ldmx4(uint32_t addr, uint32_t& r0, uint32_t& r1, uint32_t& r2, uint32_t& r3) {
    asm volatile("ldmatrix.sync.aligned.m8n8.x4.shared.b16 {%0,%1,%2,%3}, [%4];"
                 : "=r"(r0), "=r"(r1), "=r"(r2), "=r"(r3) : "r"(addr));
}
__device__ __forceinline__ void ldmx4t(uint32_t addr, uint32_t& r0, uint32_t& r1, uint32_t& r2, uint32_t& r3) {
    asm volatile("ldmatrix.sync.aligned.m8n8.x4.trans.shared.b16 {%0,%1,%2,%3}, [%4];"
                 : "=r"(r0), "=r"(r1), "=r"(r2), "=r"(r3) : "r"(addr));
}
__device__ __forceinline__ void mma_bf16(float& d0, float& d1, float& d2, float& d3,
                                         uint32_t a0, uint32_t a1, uint32_t a2, uint32_t a3,
                                         uint32_t b0, uint32_t b1) {
    asm volatile("mma.sync.aligned.m16n8k16.row.col.f32.bf16.bf16.f32 "
                 "{%0,%1,%2,%3},{%4,%5,%6,%7},{%8,%9},{%0,%1,%2,%3};"
                 : "+f"(d0), "+f"(d1), "+f"(d2), "+f"(d3)
                 : "r"(a0), "r"(a1), "r"(a2), "r"(a3), "r"(b0), "r"(b1));
}
__device__ __forceinline__ uint4 lds128(uint32_t addr) {
    uint4 v;
    asm volatile("ld.shared.v4.b32 {%0,%1,%2,%3}, [%4];"
                 : "=r"(v.x), "=r"(v.y), "=r"(v.z), "=r"(v.w) : "r"(addr));
    return v;
}

__global__ void __launch_bounds__(512, 1)
wfr_kernel(const float* __restrict__ D, float* __restrict__ out)
{
    extern __shared__ char smraw[];
    Smem* sm = reinterpret_cast<Smem*>(smraw);
    const int b = blockIdx.x;
    const int t = threadIdx.x;
    const float* __restrict__ Db = D + (size_t)b * (NN * NN);

    // ---------------- Prologue: K0 = (cos(min(2D,pi/2)) + 1e-5)^20  (bf16, SMEM) ---------
    {
        const float4* __restrict__ D4 = reinterpret_cast<const float4*>(Db);
        #pragma unroll 4
        for (int k = 0; k < 32; k++) {
            int i4 = t + k * 512;
            float4 d = D4[i4];
            int e = i4 << 2;
            int i = e >> 8, j = e & (NN - 1);
            float c0 = __cosf(fminf(d.x * 2.0f, PI2F)) + 1e-5f;
            float c1 = __cosf(fminf(d.y * 2.0f, PI2F)) + 1e-5f;
            float c2 = __cosf(fminf(d.z * 2.0f, PI2F)) + 1e-5f;
            float c3 = __cosf(fminf(d.w * 2.0f, PI2F)) + 1e-5f;
            float k0 = exp2f(20.0f * __log2f(c0));
            float k1 = exp2f(20.0f * __log2f(c1));
            float k2 = exp2f(20.0f * __log2f(c2));
            float k3 = exp2f(20.0f * __log2f(c3));
            uint2 pk = make_uint2(pack_bf16(k0, k1), pack_bf16(k2, k3));
            *reinterpret_cast<uint2*>(&sm->K0[i * KPAD + j]) = pk;
        }
        if (t < NN / 2) reinterpret_cast<uint32_t*>(sm->zbp)[t] = 0x3F803F80u; // z = 1.0
    }
    __syncthreads();

    const int lane    = t & 31;
    const int wp      = t >> 5;         // 16 warps
    const int rowbase = wp << 4;        // 16 rows per warp
    const bool owner  = (lane & 3) == 0;
    const int  oidx   = rowbase + (lane >> 2);
    const int  q      = lane & 3;

    uint16_t* zb16 = sm->zbp;
    uint16_t* wb16 = sm->wbp;
    const int po0 = pidx2(oidx), po1 = pidx2(oidx + 8);

    const uint32_t k0base = (uint32_t)__cvta_generic_to_shared(sm->K0);
    const uint32_t addrRow = k0base + 2u * ((rowbase + (lane & 15)) * KPAD + ((lane >> 4) << 3));
    const uint32_t addrCol = k0base + 2u * (((lane & 7) + ((lane & 16) >> 1)) * KPAD + rowbase + (lane & 8));
    const uint32_t zbase = (uint32_t)__cvta_generic_to_shared(sm->zbp) + q * 16;
    const uint32_t wbase = (uint32_t)__cvta_generic_to_shared(sm->wbp) + q * 16;

    // ---- load row-pass A fragments ONCE (K0 is iteration-invariant) ----
    uint32_t A0[16], A1[16], A2[16], A3[16];
    #pragma unroll
    for (int cc = 0; cc < 16; cc++)
        ldmx4(addrRow + cc * 32, A0[cc], A1[cc], A2[cc], A3[cc]);

    float u0 = 0.0f, u1 = 0.0f;         // owner-lane row potentials
    float w0f = 1.0f, w1f = 1.0f;
    float v0 = 0.0f, v1 = 0.0f;         // owner-lane col potentials
    float z0f = 1.0f, z1f = 1.0f, c0s = 0.0f, c1s = 0.0f;

    // ---------------- 50 Sinkhorn iterations (eager rescale, tensor-core matvecs) --------
    #pragma unroll 1
    for (int it = 0; it < NITER; it++) {
        // ---- row pass: r = K0 z (A-frags in registers, B via one LDS.128 per chunk pair,
        //      4 independent accumulator quads) ----
        {
            float q00 = 0.f, q01 = 0.f, q02 = 0.f, q03 = 0.f;
            float q10 = 0.f, q11 = 0.f, q12 = 0.f, q13 = 0.f;
            float q20 = 0.f, q21 = 0.f, q22 = 0.f, q23 = 0.f;
            float q30 = 0.f, q31 = 0.f, q32 = 0.f, q33 = 0.f;
            #pragma unroll
            for (int p = 0; p < 8; p++) {
                uint4 bb = lds128(zbase + p * 64);
                int cc = 2 * p;
                if ((cc & 3) == 0) {
                    mma_bf16(q00, q01, q02, q03, A0[cc], A1[cc], A2[cc], A3[cc], bb.x, bb.y);
                    mma_bf16(q10, q11, q12, q13, A0[cc+1], A1[cc+1], A2[cc+1], A3[cc+1], bb.z, bb.w);
                } else {
                    mma_bf16(q20, q21, q22, q23, A0[cc], A1[cc], A2[cc], A3[cc], bb.x, bb.y);
                    mma_bf16(q30, q31, q32, q33, A0[cc+1], A1[cc+1], A2[cc+1], A3[cc+1], bb.z, bb.w);
                }
            }
            float r0 = (q00 + q10) + (q20 + q30);   // row oidx
            float r1 = (q02 + q12) + (q22 + q32);   // row oidx+8
            float la0 = fminf(-PCOEF * (11.0f * u0 + __logf(DYC * r0)), LOGHUGE);
            float la1 = fminf(-PCOEF * (11.0f * u1 + __logf(DYC * r1)), LOGHUGE);
            u0 += EPSF * la0;
            u1 += EPSF * la1;
            w0f = __expf(10.0f * u0);
            w1f = __expf(10.0f * u1);
            if (owner) {
                wb16[po0] = to_bf16u(w0f);
                wb16[po1] = to_bf16u(w1f);
            }
        }
        __syncthreads();

        // ---- col pass: c = K0^T w (streamed transposed ldmatrix; B via LDS.128) ----
        {
            float d0 = 0.f, d1 = 0.f, d2 = 0.f, d3 = 0.f;
            float e0 = 0.f, e1 = 0.f, e2 = 0.f, e3 = 0.f;
            #pragma unroll
            for (int p = 0; p < 8; p++) {
                uint4 bb = lds128(wbase + p * 64);
                int cc = 2 * p;
                uint32_t a0, a1, a2, a3;
                ldmx4t(addrCol + cc * (16 * 2 * KPAD), a0, a1, a2, a3);
                mma_bf16(d0, d1, d2, d3, a0, a1, a2, a3, bb.x, bb.y);
                ldmx4t(addrCol + (cc + 1) * (16 * 2 * KPAD), a0, a1, a2, a3);
                mma_bf16(e0, e1, e2, e3, a0, a1, a2, a3, bb.z, bb.w);
            }
            float c0 = d0 + e0;      // col oidx
            float c1 = d2 + e2;      // col oidx+8
            c0s = c0; c1s = c1;
            float lb0 = fminf(-PCOEF * (11.0f * v0 + __logf(DXC * c0)), LOGHUGE);
            float lb1 = fminf(-PCOEF * (11.0f * v1 + __logf(DXC * c1)), LOGHUGE);
            v0 += EPSF * lb0;
            v1 += EPSF * lb1;
            z0f = __expf(10.0f * v0);
            z1f = __expf(10.0f * v1);
            if (owner) {
                zb16[po0] = to_bf16u(z0f);
                zb16[po1] = to_bf16u(z1f);
            }
        }
        __syncthreads();
    }

    // publish final f32 state for the epilogue
    if (owner) {
        sm->w[oidx]     = w0f;  sm->w[oidx + 8]     = w1f;
        sm->z[oidx]     = z0f;  sm->z[oidx + 8]     = z1f;
        sm->csave[oidx] = c0s;  sm->csave[oidx + 8] = c1s;
    }
    __syncthreads();

    // ---------------- Epilogue: marginals + transport --------------------------------
    const int row = t & (NN - 1);
    const int h   = t >> 8;
    {
        const uint16_t* __restrict__ kr = sm->K0 + row * KPAD + h * 128;
        const float*    __restrict__ zh = sm->z + h * 128;
        const float*    __restrict__ dr = Db + row * NN + h * 128;
        float racc = 0.f, tacc = 0.f;
        #pragma unroll 4
        for (int c = 0; c < 16; c++) {
            uint4  k4 = *reinterpret_cast<const uint4*>(kr + c * 8);
            float4 z0 = *reinterpret_cast<const float4*>(zh + c * 8);
            float4 z1 = *reinterpret_cast<const float4*>(zh + c * 8 + 4);
            float4 d0 = *reinterpret_cast<const float4*>(dr + c * 8);
            float4 d1 = *reinterpret_cast<const float4*>(dr + c * 8 + 4);

            float kz, cc, Cv;
            kz = __uint_as_float(k4.x << 16)          * z0.x; racc += kz;
            cc = __cosf(fminf(d0.x * 2.0f, PI2F)) + 1e-5f; Cv = -2.0f * __logf(cc); tacc = fmaf(kz, Cv, tacc);
            kz = __uint_as_float(k4.x & 0xFFFF0000u)  * z0.y; racc += kz;
            cc = __cosf(fminf(d0.y * 2.0f, PI2F)) + 1e-5f; Cv = -2.0f * __logf(cc); tacc = fmaf(kz, Cv, tacc);
            kz = __uint_as_float(k4.y << 16)          * z0.z; racc += kz;
            cc = __cosf(fminf(d0.z * 2.0f, PI2F)) + 1e-5f; Cv = -2.0f * __logf(cc); tacc = fmaf(kz, Cv, tacc);
            kz = __uint_as_float(k4.y & 0xFFFF0000u)  * z0.w; racc += kz;
            cc = __cosf(fminf(d0.w * 2.0f, PI2F)) + 1e-5f; Cv = -2.0f * __logf(cc); tacc = fmaf(kz, Cv, tacc);
            kz = __uint_as_float(k4.z << 16)          * z1.x; racc += kz;
            cc = __cosf(fminf(d1.x * 2.0f, PI2F)) + 1e-5f; Cv = -2.0f * __logf(cc); tacc = fmaf(kz, Cv, tacc);
            kz = __uint_as_float(k4.z & 0xFFFF0000u)  * z1.y; racc += kz;
            cc = __cosf(fminf(d1.y * 2.0f, PI2F)) + 1e-5f; Cv = -2.0f * __logf(cc); tacc = fmaf(kz, Cv, tacc);
            kz = __uint_as_float(k4.w << 16)          * z1.z; racc += kz;
            cc = __cosf(fminf(d1.z * 2.0f, PI2F)) + 1e-5f; Cv = -2.0f * __logf(cc); tacc = fmaf(kz, Cv, tacc);
            kz = __uint_as_float(k4.w & 0xFFFF0000u)  * z1.w; racc += kz;
            cc = __cosf(fminf(d1.w * 2.0f, PI2F)) + 1e-5f; Cv = -2.0f * __logf(cc); tacc = fmaf(kz, Cv, tacc);
        }
        sm->part[h][row]     = racc;
        sm->part[2 + h][row] = tacc;
    }
    __syncthreads();

    float val = 0.0f;
    if (t < NN) {
        float w_  = sm->w[t];
        float rm  = DYC * w_ * (sm->part[0][t] + sm->part[1][t]);
        float klr = rm * __logf(rm + 1e-10f) - rm + 1.0f;
        float tp  = w_ * (sm->part[2][t] + sm->part[3][t]) * (DXC * DYC);
        float cm  = DXC * sm->z[t] * sm->csave[t];
        float klc = cm * __logf(cm + 1e-10f) - cm + 1.0f;
        val = klr * DXC + klc * DYC + tp;
    }
    #pragma unroll
    for (int o = 16; o; o >>= 1) val += __shfl_down_sync(0xFFFFFFFFu, val, o);
    if (t < NN && lane == 0) sm->red[wp] = val;
    __syncthreads();
    if (t == 0) {
        float s = 0.0f;
        #pragma unroll
        for (int i = 0; i < 8; i++) s += sm->red[i];
        out[b] = s;
    }
}

extern "C" void kernel_launch(void* const* d_in, const int* in_sizes, int n_in,
                              void* d_out, int out_size)
{
    const float* D = (const float*)d_in[0];
    float* out = (float*)d_out;
    (void)in_sizes; (void)n_in; (void)out_size;
    size_t smem = sizeof(Smem);
    cudaFuncSetAttribute(wfr_kernel, cudaFuncAttributeMaxDynamicSharedMemorySize, (int)smem);
    wfr_kernel<<<NB, 512, smem>>>(D, out);
}